// round 13
// baseline (speedup 1.0000x reference)
#include <cuda_runtime.h>
#include <cstdint>

#define NN 100000
#define NE 800000
#define FIN 128
#define HID 64

static __device__ __constant__ float d_SCALE = 0.70710678118654752440f;
#define BN_EPS 1e-5f

// ---------------- scratch (device globals; no allocation) ----------------
__device__ float g_h0[NN * HID];   // fc output, later reused for h2
__device__ float g_t[NN * HID];    // (h @ w) * dego^-1/2
__device__ float g_agg[NN * HID];  // scatter-add accumulator
__device__ float g_h1[NN * HID];   // conv1 output
__device__ int   g_dego[NN];
__device__ int   g_degi[NN];
__device__ float g_sum[HID];
__device__ float g_ssq[HID];
__device__ float g_bna[HID];
__device__ float g_bnc[HID];

// packed fp32x2 FMA
#define FMA2(acc, a, b) \
    asm("fma.rn.f32x2 %0, %1, %2, %0;" : "+l"(acc) : "l"(a), "l"(b))
#define PACK_DUP(dst, fval) \
    asm("mov.b64 %0, {%1, %1};" : "=l"(dst) : "r"(__float_as_uint(fval)))
#define UNPACK2(lo, hi, p) \
    asm("mov.b64 {%0, %1}, %2;" : "=f"(lo), "=f"(hi) : "l"(p))

// ---------------- init: zero agg + degrees + BN accumulators ----------------
__global__ void k_init() {
    int i = blockIdx.x * blockDim.x + threadIdx.x;
    if (i < NN * (HID / 4))
        ((float4*)g_agg)[i] = make_float4(0.f, 0.f, 0.f, 0.f);
    if (i < NN) { g_dego[i] = 0; g_degi[i] = 0; }
    if (i < HID) { g_sum[i] = 0.f; g_ssq[i] = 0.f; }
}

// ---------------- degree counting ----------------
__global__ void k_degree(const int* __restrict__ src, const int* __restrict__ dst) {
    int e = blockIdx.x * blockDim.x + threadIdx.x;
    if (e < NE) {
        atomicAdd(&g_dego[src[e]], 1);
        atomicAdd(&g_degi[dst[e]], 1);
    }
}

// shared inner-product loop: acc += At-tile @ Ws-tile over 64 k
__device__ __forceinline__ void mma64(unsigned long long acc[4][4],
                                      const float At[64][128],
                                      const float Ws[64][HID],
                                      int tr, int tc) {
#pragma unroll 16
    for (int kk = 0; kk < 64; kk++) {
        unsigned long long bp[4];
        bp[0] = *(const unsigned long long*)&Ws[kk][tc + 0];
        bp[1] = *(const unsigned long long*)&Ws[kk][tc + 2];
        bp[2] = *(const unsigned long long*)&Ws[kk][tc + 4];
        bp[3] = *(const unsigned long long*)&Ws[kk][tc + 6];
        float4 a = *(const float4*)&At[kk][tr];
        float aa[4] = {a.x, a.y, a.z, a.w};
#pragma unroll
        for (int i = 0; i < 4; i++) {
            unsigned long long ad;
            PACK_DUP(ad, aa[i]);
#pragma unroll
            for (int j = 0; j < 4; j++) FMA2(acc[i][j], ad, bp[j]);
        }
    }
}

// write t-epilogue: t[r] = acc * dego[r]^-1/2
__device__ __forceinline__ void epi_t(unsigned long long acc[4][4],
                                      int r0, int tr, int tc) {
#pragma unroll
    for (int i = 0; i < 4; i++) {
        int r = r0 + tr + i;
        if (r < NN) {
            float c0, c1, c2, c3, c4, c5, c6, c7;
            UNPACK2(c0, c1, acc[i][0]);
            UNPACK2(c2, c3, acc[i][1]);
            UNPACK2(c4, c5, acc[i][2]);
            UNPACK2(c6, c7, acc[i][3]);
            float sc = rsqrtf((float)max(g_dego[r], 1));
            float4 o0, o1;
            o0.x = c0 * sc; o0.y = c1 * sc; o0.z = c2 * sc; o0.w = c3 * sc;
            o1.x = c4 * sc; o1.y = c5 * sc; o1.z = c6 * sc; o1.w = c7 * sc;
            *((float4*)&g_t[(size_t)r * HID + tc]) = o0;
            *((float4*)&g_t[(size_t)r * HID + tc + 4]) = o1;
        }
    }
}

// ======= fused fc + conv1-GEMM =======
// h0 = x @ fc_w + fc_b  (K=128, written to gmem AND restaged in smem)
// t  = (h0 @ w1) * dego^-1/2
__global__ __launch_bounds__(256) void k_fc1(const float* __restrict__ x,
                                             const float* __restrict__ fc_w,
                                             const float* __restrict__ fc_b,
                                             const float* __restrict__ w1) {
    __shared__ __align__(16) float At[64][128];   // 32 KB
    __shared__ __align__(16) float Ws[64][HID];   // 16 KB

    const int t = threadIdx.x;
    const int lane = t & 31;
    const int warp = t >> 5;
    const int r0 = blockIdx.x * 128;
    const int tr = lane * 4;
    const int tc = warp * 8;

    unsigned long long acc[4][4];
#pragma unroll
    for (int i = 0; i < 4; i++)
#pragma unroll
        for (int j = 0; j < 4; j++) acc[i][j] = 0ULL;

    const int arow = t & 127;
    const int ahalf = t >> 7;
    const int rload = min(r0 + arow, NN - 1);
    const float4* A4 = (const float4*)(x + (size_t)rload * FIN);
    const float4* W4 = (const float4*)fc_w;

    float4 bb0 = __ldg((const float4*)&fc_b[tc]);
    float4 bb1 = __ldg((const float4*)&fc_b[tc + 4]);

    // --- GEMM0: K=128, 2 chunks with prefetch ---
    float4 va[8], vw[4];
#pragma unroll
    for (int j = 0; j < 8; j++) va[j] = A4[ahalf * 8 + j];
#pragma unroll
    for (int j = 0; j < 4; j++) {
        int idx = t + j * 256;
        vw[j] = W4[(idx >> 4) * (HID / 4) + (idx & 15)];
    }
#pragma unroll
    for (int ch = 0; ch < 2; ch++) {
        if (ch > 0) __syncthreads();
#pragma unroll
        for (int j = 0; j < 8; j++) {
            At[ahalf * 32 + 4 * j + 0][arow] = va[j].x;
            At[ahalf * 32 + 4 * j + 1][arow] = va[j].y;
            At[ahalf * 32 + 4 * j + 2][arow] = va[j].z;
            At[ahalf * 32 + 4 * j + 3][arow] = va[j].w;
        }
#pragma unroll
        for (int j = 0; j < 4; j++) {
            int idx = t + j * 256;
            *((float4*)&Ws[idx >> 4][(idx & 15) * 4]) = vw[j];
        }
        __syncthreads();
        if (ch == 0) {
#pragma unroll
            for (int j = 0; j < 8; j++) va[j] = A4[16 + ahalf * 8 + j];
#pragma unroll
            for (int j = 0; j < 4; j++) {
                int idx = t + j * 256;
                vw[j] = W4[(64 + (idx >> 4)) * (HID / 4) + (idx & 15)];
            }
        }
        mma64(acc, At, Ws, tr, tc);
    }

    // prefetch w1 while finishing epilogue
#pragma unroll
    for (int j = 0; j < 4; j++) {
        int idx = t + j * 256;
        vw[j] = ((const float4*)w1)[(idx >> 4) * (HID / 4) + (idx & 15)];
    }

    __syncthreads();   // everyone done reading At/Ws before overwrite

    // --- epilogue0: h0 = acc + bias -> gmem + restage into At (k-major) ---
#pragma unroll
    for (int i = 0; i < 4; i++) {
        float c0, c1, c2, c3, c4, c5, c6, c7;
        UNPACK2(c0, c1, acc[i][0]);
        UNPACK2(c2, c3, acc[i][1]);
        UNPACK2(c4, c5, acc[i][2]);
        UNPACK2(c6, c7, acc[i][3]);
        c0 += bb0.x; c1 += bb0.y; c2 += bb0.z; c3 += bb0.w;
        c4 += bb1.x; c5 += bb1.y; c6 += bb1.z; c7 += bb1.w;
        int r = r0 + tr + i;
        if (r < NN) {
            float4 o0 = make_float4(c0, c1, c2, c3);
            float4 o1 = make_float4(c4, c5, c6, c7);
            *((float4*)&g_h0[(size_t)r * HID + tc]) = o0;
            *((float4*)&g_h0[(size_t)r * HID + tc + 4]) = o1;
        }
        At[tc + 0][tr + i] = c0; At[tc + 1][tr + i] = c1;
        At[tc + 2][tr + i] = c2; At[tc + 3][tr + i] = c3;
        At[tc + 4][tr + i] = c4; At[tc + 5][tr + i] = c5;
        At[tc + 6][tr + i] = c6; At[tc + 7][tr + i] = c7;
    }
#pragma unroll
    for (int j = 0; j < 4; j++) {
        int idx = t + j * 256;
        *((float4*)&Ws[idx >> 4][(idx & 15) * 4]) = vw[j];
    }
    __syncthreads();

    // --- GEMM1: t = (h0 @ w1) * nrmo ---
#pragma unroll
    for (int i = 0; i < 4; i++)
#pragma unroll
        for (int j = 0; j < 4; j++) acc[i][j] = 0ULL;
    mma64(acc, At, Ws, tr, tc);
    epi_t(acc, r0, tr, tc);
}

// ======= fused combine1 + conv2-GEMM =======
// h1 = (h0 + agg*nrmi + b1) * SCALE  (written to gmem, agg re-zeroed, staged)
// t  = (h1 @ w2) * dego^-1/2
__global__ __launch_bounds__(256) void k_cg2(const float* __restrict__ b1,
                                             const float* __restrict__ w2) {
    __shared__ __align__(16) float At[64][128];
    __shared__ __align__(16) float Ws[64][HID];

    const int t = threadIdx.x;
    const int lane = t & 31;
    const int warp = t >> 5;
    const int r0 = blockIdx.x * 128;
    const int tr = lane * 4;
    const int tc = warp * 8;

    const int arow = t & 127;
    const int half = t >> 7;           // which 32-col half of the row
    const int row = r0 + arow;
    const int rl = min(row, NN - 1);
    const size_t base = (size_t)rl * (HID / 4) + half * 8;   // float4 index

    float nd = rsqrtf((float)max(g_degi[rl], 1));
    float scl = d_SCALE;
    const float4* H04 = (const float4*)g_h0;
    const float4* AG4 = (const float4*)g_agg;
    const float4* B14 = (const float4*)b1;

#pragma unroll
    for (int j = 0; j < 8; j++) {
        float4 h = H04[base + j];
        float4 a = AG4[base + j];
        float4 b = __ldg(&B14[half * 8 + j]);
        float4 v;
        v.x = (h.x + a.x * nd + b.x) * scl;
        v.y = (h.y + a.y * nd + b.y) * scl;
        v.z = (h.z + a.z * nd + b.z) * scl;
        v.w = (h.w + a.w * nd + b.w) * scl;
        if (row < NN) {
            ((float4*)g_h1)[base + j] = v;
            ((float4*)g_agg)[base + j] = make_float4(0.f, 0.f, 0.f, 0.f);
        }
        int k = half * 32 + j * 4;
        At[k + 0][arow] = v.x;
        At[k + 1][arow] = v.y;
        At[k + 2][arow] = v.z;
        At[k + 3][arow] = v.w;
    }
#pragma unroll
    for (int j = 0; j < 4; j++) {
        int idx = t + j * 256;
        *((float4*)&Ws[idx >> 4][(idx & 15) * 4]) =
            ((const float4*)w2)[(idx >> 4) * (HID / 4) + (idx & 15)];
    }
    __syncthreads();

    unsigned long long acc[4][4];
#pragma unroll
    for (int i = 0; i < 4; i++)
#pragma unroll
        for (int j = 0; j < 4; j++) acc[i][j] = 0ULL;
    mma64(acc, At, Ws, tr, tc);
    epi_t(acc, r0, tr, tc);
}

// ---------------- edge scatter: agg[dst] += t[src]  (16 threads / edge, v4 red) ----------------
__global__ void k_scatter(const int* __restrict__ src, const int* __restrict__ dst) {
    int idx = blockIdx.x * blockDim.x + threadIdx.x;
    if (idx >= NE * (HID / 4)) return;
    int e = idx >> 4;
    int c = idx & 15;
    int s = __ldg(&src[e]);
    int d = __ldg(&dst[e]);
    float4 v = ((const float4*)g_t)[s * 16 + c];
    float* p = &g_agg[d * HID + c * 4];
    asm volatile("red.global.add.v4.f32 [%0], {%1,%2,%3,%4};"
                 :: "l"(p), "f"(v.x), "f"(v.y), "f"(v.z), "f"(v.w)
                 : "memory");
}

// ------- combine2 + BN partial sums: h2 -> g_h0, accumulate sum/sumsq (float4) -------
__global__ __launch_bounds__(256) void k_combine2_bn(const float* __restrict__ b2) {
    const int T = gridDim.x * blockDim.x;       // multiple of 16
    int tg = blockIdx.x * blockDim.x + threadIdx.x;
    int c4 = tg & 15;
    float4 bb = ((const float4*)b2)[c4];
    float scl = d_SCALE;
    float4 s = make_float4(0.f, 0.f, 0.f, 0.f);
    float4 ss = make_float4(0.f, 0.f, 0.f, 0.f);
    for (int idx = tg; idx < NN * (HID / 4); idx += T) {
        int row = idx >> 4;
        float4 h = ((const float4*)g_h1)[idx];
        float4 a = ((const float4*)g_agg)[idx];
        float nd = rsqrtf((float)max(g_degi[row], 1));
        float4 v;
        v.x = (h.x + a.x * nd + bb.x) * scl;
        v.y = (h.y + a.y * nd + bb.y) * scl;
        v.z = (h.z + a.z * nd + bb.z) * scl;
        v.w = (h.w + a.w * nd + bb.w) * scl;
        ((float4*)g_h0)[idx] = v;
        s.x += v.x; s.y += v.y; s.z += v.z; s.w += v.w;
        ss.x += v.x * v.x; ss.y += v.y * v.y; ss.z += v.z * v.z; ss.w += v.w * v.w;
    }
    __shared__ float4 sh[256];
    sh[threadIdx.x] = s;
    __syncthreads();
    if (threadIdx.x < 16) {
        float4 tot = sh[threadIdx.x];
#pragma unroll
        for (int j = 1; j < 16; j++) {
            float4 o = sh[threadIdx.x + j * 16];
            tot.x += o.x; tot.y += o.y; tot.z += o.z; tot.w += o.w;
        }
        atomicAdd(&g_sum[threadIdx.x * 4 + 0], tot.x);
        atomicAdd(&g_sum[threadIdx.x * 4 + 1], tot.y);
        atomicAdd(&g_sum[threadIdx.x * 4 + 2], tot.z);
        atomicAdd(&g_sum[threadIdx.x * 4 + 3], tot.w);
    }
    __syncthreads();
    sh[threadIdx.x] = ss;
    __syncthreads();
    if (threadIdx.x < 16) {
        float4 tot = sh[threadIdx.x];
#pragma unroll
        for (int j = 1; j < 16; j++) {
            float4 o = sh[threadIdx.x + j * 16];
            tot.x += o.x; tot.y += o.y; tot.z += o.z; tot.w += o.w;
        }
        atomicAdd(&g_ssq[threadIdx.x * 4 + 0], tot.x);
        atomicAdd(&g_ssq[threadIdx.x * 4 + 1], tot.y);
        atomicAdd(&g_ssq[threadIdx.x * 4 + 2], tot.z);
        atomicAdd(&g_ssq[threadIdx.x * 4 + 3], tot.w);
    }
}

__global__ void k_bn_final(const float* __restrict__ gamma, const float* __restrict__ beta) {
    int f = threadIdx.x;
    float mu = g_sum[f] * (1.0f / NN);
    float var = g_ssq[f] * (1.0f / NN) - mu * mu;
    float a = gamma[f] * rsqrtf(var + BN_EPS);
    g_bna[f] = a;
    g_bnc[f] = beta[f] - mu * a;
}

__global__ void k_out(float* __restrict__ out) {
    int idx = blockIdx.x * blockDim.x + threadIdx.x;
    if (idx >= NN * (HID / 4)) return;
    int c4 = idx & 15;
    float4 h = ((const float4*)g_h0)[idx];
    float4 a = ((const float4*)g_bna)[c4];
    float4 c = ((const float4*)g_bnc)[c4];
    float4 r;
    r.x = h.x * a.x + c.x;
    r.y = h.y * a.y + c.y;
    r.z = h.z * a.z + c.z;
    r.w = h.w * a.w + c.w;
    ((float4*)out)[idx] = r;
}

// ---------------- launch ----------------
extern "C" void kernel_launch(void* const* d_in, const int* in_sizes, int n_in,
                              void* d_out, int out_size) {
    const int* src = (const int*)d_in[0];
    const int* dst = (const int*)d_in[1];
    const float* x = (const float*)d_in[2];
    const float* fc_w = (const float*)d_in[3];
    const float* fc_b = (const float*)d_in[4];
    const float* w1 = (const float*)d_in[5];
    const float* b1 = (const float*)d_in[6];
    const float* w2 = (const float*)d_in[7];
    const float* b2 = (const float*)d_in[8];
    const float* gamma = (const float*)d_in[9];
    const float* beta = (const float*)d_in[10];
    float* out = (float*)d_out;

    const int nb_vec = (NN * (HID / 4) + 255) / 256;     // 6250
    const int nb_edge = (NE + 255) / 256;
    const int nb_scat = (NE * (HID / 4) + 255) / 256;    // 50000
    const int nb_gemm = (NN + 127) / 128;                // 782

    k_init<<<nb_vec, 256>>>();
    k_degree<<<nb_edge, 256>>>(src, dst);

    // fc + conv1 GEMM fused: h0 + t
    k_fc1<<<nb_gemm, 256>>>(x, fc_w, fc_b, w1);
    k_scatter<<<nb_scat, 256>>>(src, dst);

    // combine1 + conv2 GEMM fused: h1 (+agg re-zero) + t
    k_cg2<<<nb_gemm, 256>>>(b1, w2);
    k_scatter<<<nb_scat, 256>>>(src, dst);

    k_combine2_bn<<<256, 256>>>(b2);                     // h2 -> g_h0, BN partials
    k_bn_final<<<1, 64>>>(gamma, beta);
    k_out<<<nb_vec, 256>>>(out);
}

// round 14
// speedup vs baseline: 1.1897x; 1.1897x over previous
#include <cuda_runtime.h>
#include <cstdint>

#define NN 100000
#define NE 800000
#define FIN 128
#define HID 64
#define NB_SCAN ((NN + 255) / 256)   // 391
#define EPT 8                        // edges per thread in sorted scatter

static __device__ __constant__ float d_SCALE = 0.70710678118654752440f;
#define BN_EPS 1e-5f

// ---------------- scratch (device globals; no allocation) ----------------
__device__ float g_h0[NN * HID];   // fc output, later reused for h2
__device__ float g_t[NN * HID];    // (h @ w) * dego^-1/2
__device__ float g_agg[NN * HID];  // scatter-add accumulator
__device__ float g_h1[NN * HID];   // conv1 output
__device__ int   g_dego[NN];
__device__ int   g_degi[NN];
__device__ int   g_cursor[NN];
__device__ int   g_esrc[NE];       // src sorted by dst
__device__ int   g_edst[NE];       // dst sorted (bucket id per slot)
__device__ int   g_bsum[NB_SCAN];
__device__ int   g_boff[512];
__device__ float g_sum[HID];
__device__ float g_ssq[HID];
__device__ float g_bna[HID];
__device__ float g_bnc[HID];

// packed fp32x2 FMA
#define FMA2(acc, a, b) \
    asm("fma.rn.f32x2 %0, %1, %2, %0;" : "+l"(acc) : "l"(a), "l"(b))
#define PACK_DUP(dst, fval) \
    asm("mov.b64 %0, {%1, %1};" : "=l"(dst) : "r"(__float_as_uint(fval)))
#define UNPACK2(lo, hi, p) \
    asm("mov.b64 {%0, %1}, %2;" : "=f"(lo), "=f"(hi) : "l"(p))

// ---------------- init: zero agg + degrees + BN accumulators ----------------
__global__ void k_init() {
    int i = blockIdx.x * blockDim.x + threadIdx.x;
    if (i < NN * (HID / 4))
        ((float4*)g_agg)[i] = make_float4(0.f, 0.f, 0.f, 0.f);
    if (i < NN) { g_dego[i] = 0; g_degi[i] = 0; }
    if (i < HID) { g_sum[i] = 0.f; g_ssq[i] = 0.f; }
}

// ---------------- degree counting ----------------
__global__ void k_degree(const int* __restrict__ src, const int* __restrict__ dst) {
    int e = blockIdx.x * blockDim.x + threadIdx.x;
    if (e < NE) {
        atomicAdd(&g_dego[src[e]], 1);
        atomicAdd(&g_degi[dst[e]], 1);
    }
}

// ---------------- CSR-ish build: scan of deg_in, counting-sort fill ----------------
__global__ void k_scanA() {
    __shared__ int sh[256];
    int i = blockIdx.x * 256 + threadIdx.x;
    sh[threadIdx.x] = (i < NN) ? g_degi[i] : 0;
    __syncthreads();
    for (int off = 128; off; off >>= 1) {
        if (threadIdx.x < off) sh[threadIdx.x] += sh[threadIdx.x + off];
        __syncthreads();
    }
    if (threadIdx.x == 0) g_bsum[blockIdx.x] = sh[0];
}

__global__ void k_scanB() {
    __shared__ int sh[512];
    int t = threadIdx.x;
    int v = (t < NB_SCAN) ? g_bsum[t] : 0;
    sh[t] = v;
    __syncthreads();
    for (int off = 1; off < 512; off <<= 1) {
        int a = (t >= off) ? sh[t - off] : 0;
        __syncthreads();
        sh[t] += a;
        __syncthreads();
    }
    g_boff[t] = sh[t] - v;   // exclusive
}

__global__ void k_scanC() {
    __shared__ int sh[256];
    int t = threadIdx.x;
    int i = blockIdx.x * 256 + t;
    int v = (i < NN) ? g_degi[i] : 0;
    sh[t] = v;
    __syncthreads();
    for (int off = 1; off < 256; off <<= 1) {
        int a = (t >= off) ? sh[t - off] : 0;
        __syncthreads();
        sh[t] += a;
        __syncthreads();
    }
    int excl = sh[t] - v + g_boff[blockIdx.x];
    if (i < NN) g_cursor[i] = excl;
}

__global__ void k_fill(const int* __restrict__ src, const int* __restrict__ dst) {
    int e = blockIdx.x * blockDim.x + threadIdx.x;
    if (e < NE) {
        int d = dst[e];
        int p = atomicAdd(&g_cursor[d], 1);
        g_esrc[p] = src[e];
        g_edst[p] = d;
    }
}

// ======= packed-fp32 GEMM: C[N,64] = A[N,K] @ W[K,64], 256 thr (R10) =======
template <int MODE>
__global__ __launch_bounds__(256) void k_gemm(const float* __restrict__ Ain,
                                              const float* __restrict__ W,
                                              const float* __restrict__ bias) {
    constexpr int K = (MODE == 0) ? FIN : HID;
    constexpr int NCH = K / 64;

    __shared__ __align__(16) float At[64][128];   // 32 KB
    __shared__ __align__(16) float Ws[64][HID];   // 16 KB

    const float* A = (MODE == 0) ? Ain : ((MODE == 1) ? (const float*)g_h0
                                                      : (const float*)g_h1);
    float* C = (MODE == 0) ? (float*)g_h0 : (float*)g_t;

    const int t = threadIdx.x;
    const int lane = t & 31;
    const int warp = t >> 5;
    const int r0 = blockIdx.x * 128;
    const int tr = lane * 4;
    const int tc = warp * 8;

    unsigned long long acc[4][4];
#pragma unroll
    for (int i = 0; i < 4; i++)
#pragma unroll
        for (int j = 0; j < 4; j++) acc[i][j] = 0ULL;

    const int arow = t & 127;
    const int ahalf = t >> 7;
    const int rload = min(r0 + arow, NN - 1);
    const float4* A4 = (const float4*)(A + (size_t)rload * K);
    const float4* W4 = (const float4*)W;

    float4 bb0, bb1;
    if (MODE == 0) {
        bb0 = __ldg((const float4*)&bias[tc]);
        bb1 = __ldg((const float4*)&bias[tc + 4]);
    }

    float4 va[8], vw[4];
#pragma unroll
    for (int j = 0; j < 8; j++) va[j] = A4[ahalf * 8 + j];
#pragma unroll
    for (int j = 0; j < 4; j++) {
        int idx = t + j * 256;
        vw[j] = W4[(idx >> 4) * (HID / 4) + (idx & 15)];
    }

#pragma unroll
    for (int ch = 0; ch < NCH; ch++) {
        if (ch > 0) __syncthreads();
#pragma unroll
        for (int j = 0; j < 8; j++) {
            At[ahalf * 32 + 4 * j + 0][arow] = va[j].x;
            At[ahalf * 32 + 4 * j + 1][arow] = va[j].y;
            At[ahalf * 32 + 4 * j + 2][arow] = va[j].z;
            At[ahalf * 32 + 4 * j + 3][arow] = va[j].w;
        }
#pragma unroll
        for (int j = 0; j < 4; j++) {
            int idx = t + j * 256;
            *((float4*)&Ws[idx >> 4][(idx & 15) * 4]) = vw[j];
        }
        __syncthreads();
        if (ch + 1 < NCH) {
#pragma unroll
            for (int j = 0; j < 8; j++) va[j] = A4[16 + ahalf * 8 + j];
#pragma unroll
            for (int j = 0; j < 4; j++) {
                int idx = t + j * 256;
                vw[j] = W4[(64 + (idx >> 4)) * (HID / 4) + (idx & 15)];
            }
        }
#pragma unroll 16
        for (int kk = 0; kk < 64; kk++) {
            unsigned long long bp[4];
            bp[0] = *(const unsigned long long*)&Ws[kk][tc + 0];
            bp[1] = *(const unsigned long long*)&Ws[kk][tc + 2];
            bp[2] = *(const unsigned long long*)&Ws[kk][tc + 4];
            bp[3] = *(const unsigned long long*)&Ws[kk][tc + 6];
            float4 a = *(const float4*)&At[kk][tr];
            float aa[4] = {a.x, a.y, a.z, a.w};
#pragma unroll
            for (int i = 0; i < 4; i++) {
                unsigned long long ad;
                PACK_DUP(ad, aa[i]);
#pragma unroll
                for (int j = 0; j < 4; j++) FMA2(acc[i][j], ad, bp[j]);
            }
        }
    }

#pragma unroll
    for (int i = 0; i < 4; i++) {
        int r = r0 + tr + i;
        if (r < NN) {
            float c0, c1, c2, c3, c4, c5, c6, c7;
            UNPACK2(c0, c1, acc[i][0]);
            UNPACK2(c2, c3, acc[i][1]);
            UNPACK2(c4, c5, acc[i][2]);
            UNPACK2(c6, c7, acc[i][3]);
            float4 o0, o1;
            if (MODE == 0) {
                o0.x = c0 + bb0.x; o0.y = c1 + bb0.y;
                o0.z = c2 + bb0.z; o0.w = c3 + bb0.w;
                o1.x = c4 + bb1.x; o1.y = c5 + bb1.y;
                o1.z = c6 + bb1.z; o1.w = c7 + bb1.w;
            } else {
                float sc = rsqrtf((float)max(g_dego[r], 1));
                o0.x = c0 * sc; o0.y = c1 * sc; o0.z = c2 * sc; o0.w = c3 * sc;
                o1.x = c4 * sc; o1.y = c5 * sc; o1.z = c6 * sc; o1.w = c7 * sc;
            }
            *((float4*)&C[(size_t)r * HID + tc]) = o0;
            *((float4*)&C[(size_t)r * HID + tc + 4]) = o1;
        }
    }
}

// ======= sorted-edge segmented scatter: agg[dst] += t[src] =======
// Thread = (edge-chunk of EPT sorted edges) x (one float4 col-slice).
// Accumulates in-register across same-dst runs -> ~4x fewer REDs.
__global__ void k_scatter_sorted() {
    int idx = blockIdx.x * blockDim.x + threadIdx.x;   // exact: NE/EPT*16
    int c = idx & 15;
    int chunk = idx >> 4;
    int p0 = chunk * EPT;

    const float4* T4 = (const float4*)g_t;
    float4 acc = make_float4(0.f, 0.f, 0.f, 0.f);
    int dprev = __ldg(&g_edst[p0]);

#pragma unroll
    for (int j = 0; j < EPT; j++) {
        int p = p0 + j;
        int s = __ldg(&g_esrc[p]);
        int d = __ldg(&g_edst[p]);
        if (d != dprev) {
            float* q = &g_agg[(size_t)dprev * HID + c * 4];
            asm volatile("red.global.add.v4.f32 [%0], {%1,%2,%3,%4};"
                         :: "l"(q), "f"(acc.x), "f"(acc.y), "f"(acc.z), "f"(acc.w)
                         : "memory");
            acc = make_float4(0.f, 0.f, 0.f, 0.f);
            dprev = d;
        }
        float4 v = T4[(size_t)s * 16 + c];
        acc.x += v.x; acc.y += v.y; acc.z += v.z; acc.w += v.w;
    }
    float* q = &g_agg[(size_t)dprev * HID + c * 4];
    asm volatile("red.global.add.v4.f32 [%0], {%1,%2,%3,%4};"
                 :: "l"(q), "f"(acc.x), "f"(acc.y), "f"(acc.z), "f"(acc.w)
                 : "memory");
}

// ------- combine1: h1 = (h0 + agg*nrmi + b1) * SCALE ; re-zero agg for conv2 -------
__global__ void k_combine1(const float* __restrict__ b1) {
    int idx = blockIdx.x * blockDim.x + threadIdx.x;
    if (idx >= NN * (HID / 4)) return;
    int row = idx >> 4;
    int c4 = idx & 15;
    float4 h = ((const float4*)g_h0)[idx];
    float4 a = ((const float4*)g_agg)[idx];
    float4 b = ((const float4*)b1)[c4];
    float nd = rsqrtf((float)max(g_degi[row], 1));
    float s = d_SCALE;
    float4 r;
    r.x = (h.x + a.x * nd + b.x) * s;
    r.y = (h.y + a.y * nd + b.y) * s;
    r.z = (h.z + a.z * nd + b.z) * s;
    r.w = (h.w + a.w * nd + b.w) * s;
    ((float4*)g_h1)[idx] = r;
    ((float4*)g_agg)[idx] = make_float4(0.f, 0.f, 0.f, 0.f);
}

// ------- combine2 + BN partial sums -------
__global__ __launch_bounds__(256) void k_combine2_bn(const float* __restrict__ b2) {
    const int T = gridDim.x * blockDim.x;
    int tg = blockIdx.x * blockDim.x + threadIdx.x;
    int c4 = tg & 15;
    float4 bb = ((const float4*)b2)[c4];
    float scl = d_SCALE;
    float4 s = make_float4(0.f, 0.f, 0.f, 0.f);
    float4 ss = make_float4(0.f, 0.f, 0.f, 0.f);
    for (int idx = tg; idx < NN * (HID / 4); idx += T) {
        int row = idx >> 4;
        float4 h = ((const float4*)g_h1)[idx];
        float4 a = ((const float4*)g_agg)[idx];
        float nd = rsqrtf((float)max(g_degi[row], 1));
        float4 v;
        v.x = (h.x + a.x * nd + bb.x) * scl;
        v.y = (h.y + a.y * nd + bb.y) * scl;
        v.z = (h.z + a.z * nd + bb.z) * scl;
        v.w = (h.w + a.w * nd + bb.w) * scl;
        ((float4*)g_h0)[idx] = v;
        s.x += v.x; s.y += v.y; s.z += v.z; s.w += v.w;
        ss.x += v.x * v.x; ss.y += v.y * v.y; ss.z += v.z * v.z; ss.w += v.w * v.w;
    }
    __shared__ float4 sh[256];
    sh[threadIdx.x] = s;
    __syncthreads();
    if (threadIdx.x < 16) {
        float4 tot = sh[threadIdx.x];
#pragma unroll
        for (int j = 1; j < 16; j++) {
            float4 o = sh[threadIdx.x + j * 16];
            tot.x += o.x; tot.y += o.y; tot.z += o.z; tot.w += o.w;
        }
        atomicAdd(&g_sum[threadIdx.x * 4 + 0], tot.x);
        atomicAdd(&g_sum[threadIdx.x * 4 + 1], tot.y);
        atomicAdd(&g_sum[threadIdx.x * 4 + 2], tot.z);
        atomicAdd(&g_sum[threadIdx.x * 4 + 3], tot.w);
    }
    __syncthreads();
    sh[threadIdx.x] = ss;
    __syncthreads();
    if (threadIdx.x < 16) {
        float4 tot = sh[threadIdx.x];
#pragma unroll
        for (int j = 1; j < 16; j++) {
            float4 o = sh[threadIdx.x + j * 16];
            tot.x += o.x; tot.y += o.y; tot.z += o.z; tot.w += o.w;
        }
        atomicAdd(&g_ssq[threadIdx.x * 4 + 0], tot.x);
        atomicAdd(&g_ssq[threadIdx.x * 4 + 1], tot.y);
        atomicAdd(&g_ssq[threadIdx.x * 4 + 2], tot.z);
        atomicAdd(&g_ssq[threadIdx.x * 4 + 3], tot.w);
    }
}

__global__ void k_bn_final(const float* __restrict__ gamma, const float* __restrict__ beta) {
    int f = threadIdx.x;
    float mu = g_sum[f] * (1.0f / NN);
    float var = g_ssq[f] * (1.0f / NN) - mu * mu;
    float a = gamma[f] * rsqrtf(var + BN_EPS);
    g_bna[f] = a;
    g_bnc[f] = beta[f] - mu * a;
}

__global__ void k_out(float* __restrict__ out) {
    int idx = blockIdx.x * blockDim.x + threadIdx.x;
    if (idx >= NN * (HID / 4)) return;
    int c4 = idx & 15;
    float4 h = ((const float4*)g_h0)[idx];
    float4 a = ((const float4*)g_bna)[c4];
    float4 c = ((const float4*)g_bnc)[c4];
    float4 r;
    r.x = h.x * a.x + c.x;
    r.y = h.y * a.y + c.y;
    r.z = h.z * a.z + c.z;
    r.w = h.w * a.w + c.w;
    ((float4*)out)[idx] = r;
}

// ---------------- launch ----------------
extern "C" void kernel_launch(void* const* d_in, const int* in_sizes, int n_in,
                              void* d_out, int out_size) {
    const int* src = (const int*)d_in[0];
    const int* dst = (const int*)d_in[1];
    const float* x = (const float*)d_in[2];
    const float* fc_w = (const float*)d_in[3];
    const float* fc_b = (const float*)d_in[4];
    const float* w1 = (const float*)d_in[5];
    const float* b1 = (const float*)d_in[6];
    const float* w2 = (const float*)d_in[7];
    const float* b2 = (const float*)d_in[8];
    const float* gamma = (const float*)d_in[9];
    const float* beta = (const float*)d_in[10];
    float* out = (float*)d_out;

    const int nb_vec = (NN * (HID / 4) + 255) / 256;     // 6250
    const int nb_edge = (NE + 255) / 256;
    const int nb_gemm = (NN + 127) / 128;                // 782
    const int nb_sscat = (NE / EPT) * 16 / 256;          // 6250 (exact)

    k_init<<<nb_vec, 256>>>();
    k_degree<<<nb_edge, 256>>>(src, dst);

    // dst-sorted edge list
    k_scanA<<<NB_SCAN, 256>>>();
    k_scanB<<<1, 512>>>();
    k_scanC<<<NB_SCAN, 256>>>();
    k_fill<<<nb_edge, 256>>>(src, dst);

    // h0 = x @ fc_w + fc_b
    k_gemm<0><<<nb_gemm, 256>>>(x, fc_w, fc_b);

    // conv1
    k_gemm<1><<<nb_gemm, 256>>>(nullptr, w1, nullptr);   // t = (h0@w1)*dego^-1/2
    k_scatter_sorted<<<nb_sscat, 256>>>();
    k_combine1<<<nb_vec, 256>>>(b1);                     // h1 + re-zero agg

    // conv2
    k_gemm<2><<<nb_gemm, 256>>>(nullptr, w2, nullptr);   // t = (h1@w2)*dego^-1/2
    k_scatter_sorted<<<nb_sscat, 256>>>();
    k_combine2_bn<<<256, 256>>>(b2);                     // h2 -> g_h0, BN partials

    k_bn_final<<<1, 64>>>(gamma, beta);
    k_out<<<nb_vec, 256>>>(out);
}

// round 15
// speedup vs baseline: 1.2413x; 1.0434x over previous
#include <cuda_runtime.h>
#include <cstdint>

#define NN 100000
#define NE 800000
#define FIN 128
#define HID 64
#define NB_SCAN ((NN + 255) / 256)   // 391
#define EPT 8                        // edges per thread in sorted scatter

static __device__ __constant__ float d_SCALE = 0.70710678118654752440f;
#define BN_EPS 1e-5f

// ---------------- scratch (device globals; no allocation) ----------------
__device__ float g_h0[NN * HID];   // fc output, later reused for h2
__device__ float g_t[NN * HID];    // (h @ w) * dego^-1/2
__device__ float g_agg[NN * HID];  // scatter-add accumulator
__device__ float g_h1[NN * HID];   // conv1 output
__device__ int   g_dego[NN];
__device__ int   g_degi[NN];
__device__ int   g_cursor[NN];
__device__ int   g_esrc[NE];       // src sorted by dst
__device__ int   g_edst[NE];       // dst sorted
__device__ int   g_bsum[NB_SCAN];
__device__ int   g_boff[512];
__device__ float g_sum[HID];
__device__ float g_ssq[HID];
__device__ float g_bna[HID];
__device__ float g_bnc[HID];

// tf32 helpers (base sm_80+ PTX, no 'a'-suffix features)
__device__ __forceinline__ uint32_t f2tf32(float v) {
    uint32_t r;
    asm("cvt.rna.tf32.f32 %0, %1;" : "=r"(r) : "f"(v));
    return r;
}

#define MMA_TF32(d, A0, A1, A2, A3, B0, B1) \
    asm volatile("mma.sync.aligned.m16n8k8.row.col.f32.tf32.tf32.f32 " \
        "{%0,%1,%2,%3}, {%4,%5,%6,%7}, {%8,%9}, {%0,%1,%2,%3};" \
        : "+f"((d)[0]), "+f"((d)[1]), "+f"((d)[2]), "+f"((d)[3]) \
        : "r"(A0), "r"(A1), "r"(A2), "r"(A3), "r"(B0), "r"(B1))

// ---------------- init: zero agg + degrees + BN accumulators ----------------
__global__ void k_init() {
    int i = blockIdx.x * blockDim.x + threadIdx.x;
    if (i < NN * (HID / 4))
        ((float4*)g_agg)[i] = make_float4(0.f, 0.f, 0.f, 0.f);
    if (i < NN) { g_dego[i] = 0; g_degi[i] = 0; }
    if (i < HID) { g_sum[i] = 0.f; g_ssq[i] = 0.f; }
}

// ---------------- degree counting ----------------
__global__ void k_degree(const int* __restrict__ src, const int* __restrict__ dst) {
    int e = blockIdx.x * blockDim.x + threadIdx.x;
    if (e < NE) {
        atomicAdd(&g_dego[src[e]], 1);
        atomicAdd(&g_degi[dst[e]], 1);
    }
}

// ---------------- scan of deg_in + counting-sort fill ----------------
__global__ void k_scanA() {
    __shared__ int sh[256];
    int i = blockIdx.x * 256 + threadIdx.x;
    sh[threadIdx.x] = (i < NN) ? g_degi[i] : 0;
    __syncthreads();
    for (int off = 128; off; off >>= 1) {
        if (threadIdx.x < off) sh[threadIdx.x] += sh[threadIdx.x + off];
        __syncthreads();
    }
    if (threadIdx.x == 0) g_bsum[blockIdx.x] = sh[0];
}

__global__ void k_scanB() {
    __shared__ int sh[512];
    int t = threadIdx.x;
    int v = (t < NB_SCAN) ? g_bsum[t] : 0;
    sh[t] = v;
    __syncthreads();
    for (int off = 1; off < 512; off <<= 1) {
        int a = (t >= off) ? sh[t - off] : 0;
        __syncthreads();
        sh[t] += a;
        __syncthreads();
    }
    g_boff[t] = sh[t] - v;   // exclusive
}

__global__ void k_scanC() {
    __shared__ int sh[256];
    int t = threadIdx.x;
    int i = blockIdx.x * 256 + t;
    int v = (i < NN) ? g_degi[i] : 0;
    sh[t] = v;
    __syncthreads();
    for (int off = 1; off < 256; off <<= 1) {
        int a = (t >= off) ? sh[t - off] : 0;
        __syncthreads();
        sh[t] += a;
        __syncthreads();
    }
    int excl = sh[t] - v + g_boff[blockIdx.x];
    if (i < NN) g_cursor[i] = excl;
}

__global__ void k_fill(const int* __restrict__ src, const int* __restrict__ dst) {
    int e = blockIdx.x * blockDim.x + threadIdx.x;
    if (e < NE) {
        int d = dst[e];
        int p = atomicAdd(&g_cursor[d], 1);
        g_esrc[p] = src[e];
        g_edst[p] = d;
    }
}

// ======= tf32-split tensor-core GEMM: C[N,64] = A[N,K] @ W[K,64] =======
// Block: 128 rows x 64 cols, 8 warps (4 in M x 2 in N); warp = 32 rows x 32 cols.
// 3-term split: AhiBhi + AloBhi + AhiBlo -> ~1e-6 rel accuracy.
// A smem stride 68 (bank 4g+tig conflict-free), B stride 72 (bank 8tig+g cf).
// MODE 0: A = x,    C = g_h0, +bias            (K=128, 2 chunks)
// MODE 1: A = g_h0, C = g_t,  * dego^-1/2      (K=64)
// MODE 2: A = g_h1, C = g_t,  * dego^-1/2      (K=64)
template <int MODE>
__global__ __launch_bounds__(256) void k_gemm(const float* __restrict__ Ain,
                                              const float* __restrict__ W,
                                              const float* __restrict__ bias) {
    constexpr int K = (MODE == 0) ? FIN : HID;
    constexpr int NCH = K / 64;
    constexpr int SA = 68;
    constexpr int SB = 72;

    extern __shared__ float smem[];
    float* Ah = smem;                    // [128][SA]
    float* Al = Ah + 128 * SA;
    float* Bh = Al + 128 * SA;           // [64][SB]
    float* Bl = Bh + 64 * SB;

    const float* A = (MODE == 0) ? Ain : ((MODE == 1) ? (const float*)g_h0
                                                      : (const float*)g_h1);
    float* C = (MODE == 0) ? (float*)g_h0 : (float*)g_t;

    const int t = threadIdx.x;
    const int lane = t & 31;
    const int g = lane >> 2;        // groupID 0..7
    const int tig = lane & 3;       // thread-in-group 0..3
    const int warp = t >> 5;
    const int wm = warp & 3;        // 32-row group
    const int wn = warp >> 2;       // 32-col group
    const int r0 = blockIdx.x * 128;

    float acc[2][4][4];
#pragma unroll
    for (int m = 0; m < 2; m++)
#pragma unroll
        for (int nt = 0; nt < 4; nt++)
#pragma unroll
            for (int i = 0; i < 4; i++) acc[m][nt][i] = 0.f;

    const int arow = t & 127;
    const int khalf = t >> 7;
    const int rload = min(r0 + arow, NN - 1);
    const float4* A4 = (const float4*)(A + (size_t)rload * K);
    const float4* W4 = (const float4*)W;

#pragma unroll
    for (int ch = 0; ch < NCH; ch++) {
        if (ch > 0) __syncthreads();
        // --- stage A chunk (rows x 64k), hi/lo split, STS.128 ---
#pragma unroll
        for (int j = 0; j < 8; j++) {
            float4 v = A4[ch * 16 + khalf * 8 + j];
            uint32_t hx = f2tf32(v.x), hy = f2tf32(v.y);
            uint32_t hz = f2tf32(v.z), hw = f2tf32(v.w);
            float4 hi = make_float4(__uint_as_float(hx), __uint_as_float(hy),
                                    __uint_as_float(hz), __uint_as_float(hw));
            float4 lo = make_float4(
                __uint_as_float(f2tf32(v.x - hi.x)), __uint_as_float(f2tf32(v.y - hi.y)),
                __uint_as_float(f2tf32(v.z - hi.z)), __uint_as_float(f2tf32(v.w - hi.w)));
            int off = arow * SA + khalf * 32 + j * 4;
            *(float4*)&Ah[off] = hi;
            *(float4*)&Al[off] = lo;
        }
        // --- stage B chunk (64k x 64n) ---
#pragma unroll
        for (int j = 0; j < 4; j++) {
            int idx = t + j * 256;
            int kr = idx >> 4, c4 = idx & 15;
            float4 v = W4[(size_t)(ch * 64 + kr) * (HID / 4) + c4];
            uint32_t hx = f2tf32(v.x), hy = f2tf32(v.y);
            uint32_t hz = f2tf32(v.z), hw = f2tf32(v.w);
            float4 hi = make_float4(__uint_as_float(hx), __uint_as_float(hy),
                                    __uint_as_float(hz), __uint_as_float(hw));
            float4 lo = make_float4(
                __uint_as_float(f2tf32(v.x - hi.x)), __uint_as_float(f2tf32(v.y - hi.y)),
                __uint_as_float(f2tf32(v.z - hi.z)), __uint_as_float(f2tf32(v.w - hi.w)));
            int off = kr * SB + c4 * 4;
            *(float4*)&Bh[off] = hi;
            *(float4*)&Bl[off] = lo;
        }
        __syncthreads();

#pragma unroll
        for (int k0 = 0; k0 < 64; k0 += 8) {
            uint32_t bh0[4], bh1[4], bl0[4], bl1[4];
#pragma unroll
            for (int nt = 0; nt < 4; nt++) {
                int col = wn * 32 + nt * 8 + g;
                bh0[nt] = __float_as_uint(Bh[(k0 + tig) * SB + col]);
                bh1[nt] = __float_as_uint(Bh[(k0 + tig + 4) * SB + col]);
                bl0[nt] = __float_as_uint(Bl[(k0 + tig) * SB + col]);
                bl1[nt] = __float_as_uint(Bl[(k0 + tig + 4) * SB + col]);
            }
#pragma unroll
            for (int m = 0; m < 2; m++) {
                int rb = wm * 32 + m * 16;
                uint32_t ah0 = __float_as_uint(Ah[(rb + g) * SA + k0 + tig]);
                uint32_t ah1 = __float_as_uint(Ah[(rb + g + 8) * SA + k0 + tig]);
                uint32_t ah2 = __float_as_uint(Ah[(rb + g) * SA + k0 + tig + 4]);
                uint32_t ah3 = __float_as_uint(Ah[(rb + g + 8) * SA + k0 + tig + 4]);
                uint32_t al0 = __float_as_uint(Al[(rb + g) * SA + k0 + tig]);
                uint32_t al1 = __float_as_uint(Al[(rb + g + 8) * SA + k0 + tig]);
                uint32_t al2 = __float_as_uint(Al[(rb + g) * SA + k0 + tig + 4]);
                uint32_t al3 = __float_as_uint(Al[(rb + g + 8) * SA + k0 + tig + 4]);
#pragma unroll
                for (int nt = 0; nt < 4; nt++) {
                    MMA_TF32(acc[m][nt], ah0, ah1, ah2, ah3, bh0[nt], bh1[nt]);
                    MMA_TF32(acc[m][nt], al0, al1, al2, al3, bh0[nt], bh1[nt]);
                    MMA_TF32(acc[m][nt], ah0, ah1, ah2, ah3, bl0[nt], bl1[nt]);
                }
            }
        }
    }

    // --- epilogue ---
#pragma unroll
    for (int m = 0; m < 2; m++) {
        int r1 = r0 + wm * 32 + m * 16 + g;
        int r2 = r1 + 8;
        if (MODE == 0) {
#pragma unroll
            for (int nt = 0; nt < 4; nt++) {
                int col = wn * 32 + nt * 8 + 2 * tig;
                float2 bb = __ldg((const float2*)&bias[col]);
                if (r1 < NN) {
                    float2 o = make_float2(acc[m][nt][0] + bb.x, acc[m][nt][1] + bb.y);
                    *(float2*)&C[(size_t)r1 * HID + col] = o;
                }
                if (r2 < NN) {
                    float2 o = make_float2(acc[m][nt][2] + bb.x, acc[m][nt][3] + bb.y);
                    *(float2*)&C[(size_t)r2 * HID + col] = o;
                }
            }
        } else {
            float s1 = (r1 < NN) ? rsqrtf((float)max(g_dego[r1], 1)) : 0.f;
            float s2 = (r2 < NN) ? rsqrtf((float)max(g_dego[r2], 1)) : 0.f;
#pragma unroll
            for (int nt = 0; nt < 4; nt++) {
                int col = wn * 32 + nt * 8 + 2 * tig;
                if (r1 < NN) {
                    float2 o = make_float2(acc[m][nt][0] * s1, acc[m][nt][1] * s1);
                    *(float2*)&C[(size_t)r1 * HID + col] = o;
                }
                if (r2 < NN) {
                    float2 o = make_float2(acc[m][nt][2] * s2, acc[m][nt][3] * s2);
                    *(float2*)&C[(size_t)r2 * HID + col] = o;
                }
            }
        }
    }
}

// ======= sorted-edge segmented scatter: agg[dst] += t[src] =======
__global__ void k_scatter_sorted() {
    int idx = blockIdx.x * blockDim.x + threadIdx.x;   // exact: NE/EPT*16
    int c = idx & 15;
    int chunk = idx >> 4;
    int p0 = chunk * EPT;

    const float4* T4 = (const float4*)g_t;
    float4 acc = make_float4(0.f, 0.f, 0.f, 0.f);
    int dprev = __ldg(&g_edst[p0]);

#pragma unroll
    for (int j = 0; j < EPT; j++) {
        int p = p0 + j;
        int s = __ldg(&g_esrc[p]);
        int d = __ldg(&g_edst[p]);
        if (d != dprev) {
            float* q = &g_agg[(size_t)dprev * HID + c * 4];
            asm volatile("red.global.add.v4.f32 [%0], {%1,%2,%3,%4};"
                         :: "l"(q), "f"(acc.x), "f"(acc.y), "f"(acc.z), "f"(acc.w)
                         : "memory");
            acc = make_float4(0.f, 0.f, 0.f, 0.f);
            dprev = d;
        }
        float4 v = T4[(size_t)s * 16 + c];
        acc.x += v.x; acc.y += v.y; acc.z += v.z; acc.w += v.w;
    }
    float* q = &g_agg[(size_t)dprev * HID + c * 4];
    asm volatile("red.global.add.v4.f32 [%0], {%1,%2,%3,%4};"
                 :: "l"(q), "f"(acc.x), "f"(acc.y), "f"(acc.z), "f"(acc.w)
                 : "memory");
}

// ------- combine1: h1 = (h0 + agg*nrmi + b1) * SCALE ; re-zero agg -------
__global__ void k_combine1(const float* __restrict__ b1) {
    int idx = blockIdx.x * blockDim.x + threadIdx.x;
    if (idx >= NN * (HID / 4)) return;
    int row = idx >> 4;
    int c4 = idx & 15;
    float4 h = ((const float4*)g_h0)[idx];
    float4 a = ((const float4*)g_agg)[idx];
    float4 b = ((const float4*)b1)[c4];
    float nd = rsqrtf((float)max(g_degi[row], 1));
    float s = d_SCALE;
    float4 r;
    r.x = (h.x + a.x * nd + b.x) * s;
    r.y = (h.y + a.y * nd + b.y) * s;
    r.z = (h.z + a.z * nd + b.z) * s;
    r.w = (h.w + a.w * nd + b.w) * s;
    ((float4*)g_h1)[idx] = r;
    ((float4*)g_agg)[idx] = make_float4(0.f, 0.f, 0.f, 0.f);
}

// ------- combine2 + BN partial sums -------
__global__ __launch_bounds__(256) void k_combine2_bn(const float* __restrict__ b2) {
    const int T = gridDim.x * blockDim.x;
    int tg = blockIdx.x * blockDim.x + threadIdx.x;
    int c4 = tg & 15;
    float4 bb = ((const float4*)b2)[c4];
    float scl = d_SCALE;
    float4 s = make_float4(0.f, 0.f, 0.f, 0.f);
    float4 ss = make_float4(0.f, 0.f, 0.f, 0.f);
    for (int idx = tg; idx < NN * (HID / 4); idx += T) {
        int row = idx >> 4;
        float4 h = ((const float4*)g_h1)[idx];
        float4 a = ((const float4*)g_agg)[idx];
        float nd = rsqrtf((float)max(g_degi[row], 1));
        float4 v;
        v.x = (h.x + a.x * nd + bb.x) * scl;
        v.y = (h.y + a.y * nd + bb.y) * scl;
        v.z = (h.z + a.z * nd + bb.z) * scl;
        v.w = (h.w + a.w * nd + bb.w) * scl;
        ((float4*)g_h0)[idx] = v;
        s.x += v.x; s.y += v.y; s.z += v.z; s.w += v.w;
        ss.x += v.x * v.x; ss.y += v.y * v.y; ss.z += v.z * v.z; ss.w += v.w * v.w;
    }
    __shared__ float4 sh[256];
    sh[threadIdx.x] = s;
    __syncthreads();
    if (threadIdx.x < 16) {
        float4 tot = sh[threadIdx.x];
#pragma unroll
        for (int j = 1; j < 16; j++) {
            float4 o = sh[threadIdx.x + j * 16];
            tot.x += o.x; tot.y += o.y; tot.z += o.z; tot.w += o.w;
        }
        atomicAdd(&g_sum[threadIdx.x * 4 + 0], tot.x);
        atomicAdd(&g_sum[threadIdx.x * 4 + 1], tot.y);
        atomicAdd(&g_sum[threadIdx.x * 4 + 2], tot.z);
        atomicAdd(&g_sum[threadIdx.x * 4 + 3], tot.w);
    }
    __syncthreads();
    sh[threadIdx.x] = ss;
    __syncthreads();
    if (threadIdx.x < 16) {
        float4 tot = sh[threadIdx.x];
#pragma unroll
        for (int j = 1; j < 16; j++) {
            float4 o = sh[threadIdx.x + j * 16];
            tot.x += o.x; tot.y += o.y; tot.z += o.z; tot.w += o.w;
        }
        atomicAdd(&g_ssq[threadIdx.x * 4 + 0], tot.x);
        atomicAdd(&g_ssq[threadIdx.x * 4 + 1], tot.y);
        atomicAdd(&g_ssq[threadIdx.x * 4 + 2], tot.z);
        atomicAdd(&g_ssq[threadIdx.x * 4 + 3], tot.w);
    }
}

__global__ void k_bn_final(const float* __restrict__ gamma, const float* __restrict__ beta) {
    int f = threadIdx.x;
    float mu = g_sum[f] * (1.0f / NN);
    float var = g_ssq[f] * (1.0f / NN) - mu * mu;
    float a = gamma[f] * rsqrtf(var + BN_EPS);
    g_bna[f] = a;
    g_bnc[f] = beta[f] - mu * a;
}

__global__ void k_out(float* __restrict__ out) {
    int idx = blockIdx.x * blockDim.x + threadIdx.x;
    if (idx >= NN * (HID / 4)) return;
    int c4 = idx & 15;
    float4 h = ((const float4*)g_h0)[idx];
    float4 a = ((const float4*)g_bna)[c4];
    float4 c = ((const float4*)g_bnc)[c4];
    float4 r;
    r.x = h.x * a.x + c.x;
    r.y = h.y * a.y + c.y;
    r.z = h.z * a.z + c.z;
    r.w = h.w * a.w + c.w;
    ((float4*)out)[idx] = r;
}

// ---------------- launch ----------------
extern "C" void kernel_launch(void* const* d_in, const int* in_sizes, int n_in,
                              void* d_out, int out_size) {
    const int* src = (const int*)d_in[0];
    const int* dst = (const int*)d_in[1];
    const float* x = (const float*)d_in[2];
    const float* fc_w = (const float*)d_in[3];
    const float* fc_b = (const float*)d_in[4];
    const float* w1 = (const float*)d_in[5];
    const float* b1 = (const float*)d_in[6];
    const float* w2 = (const float*)d_in[7];
    const float* b2 = (const float*)d_in[8];
    const float* gamma = (const float*)d_in[9];
    const float* beta = (const float*)d_in[10];
    float* out = (float*)d_out;

    const int SMEM = (2 * 128 * 68 + 2 * 64 * 72) * 4;   // 106496 bytes
    cudaFuncSetAttribute(k_gemm<0>, cudaFuncAttributeMaxDynamicSharedMemorySize, SMEM);
    cudaFuncSetAttribute(k_gemm<1>, cudaFuncAttributeMaxDynamicSharedMemorySize, SMEM);
    cudaFuncSetAttribute(k_gemm<2>, cudaFuncAttributeMaxDynamicSharedMemorySize, SMEM);

    const int nb_vec = (NN * (HID / 4) + 255) / 256;     // 6250
    const int nb_edge = (NE + 255) / 256;
    const int nb_gemm = (NN + 127) / 128;                // 782
    const int nb_sscat = (NE / EPT) * 16 / 256;          // 6250 (exact)

    k_init<<<nb_vec, 256>>>();
    k_degree<<<nb_edge, 256>>>(src, dst);

    // dst-sorted edge list
    k_scanA<<<NB_SCAN, 256>>>();
    k_scanB<<<1, 512>>>();
    k_scanC<<<NB_SCAN, 256>>>();
    k_fill<<<nb_edge, 256>>>(src, dst);

    // h0 = x @ fc_w + fc_b
    k_gemm<0><<<nb_gemm, 256, SMEM>>>(x, fc_w, fc_b);

    // conv1
    k_gemm<1><<<nb_gemm, 256, SMEM>>>(nullptr, w1, nullptr);
    k_scatter_sorted<<<nb_sscat, 256>>>();
    k_combine1<<<nb_vec, 256>>>(b1);

    // conv2
    k_gemm<2><<<nb_gemm, 256, SMEM>>>(nullptr, w2, nullptr);
    k_scatter_sorted<<<nb_sscat, 256>>>();
    k_combine2_bn<<<256, 256>>>(b2);

    k_bn_final<<<1, 64>>>(gamma, beta);
    k_out<<<nb_vec, 256>>>(out);
}

// round 16
// speedup vs baseline: 1.3386x; 1.0784x over previous
#include <cuda_runtime.h>
#include <cstdint>

#define NN 100000
#define NE 800000
#define FIN 128
#define HID 64
#define NB_SCAN ((NN + 255) / 256)   // 391
#define EPT 8                        // edges per thread in sorted scatter

static __device__ __constant__ float d_SCALE = 0.70710678118654752440f;
#define BN_EPS 1e-5f

// ---------------- scratch (device globals; no allocation) ----------------
__device__ float g_h0[NN * HID];   // h0, later h2
__device__ float g_t[NN * HID];    // (h @ w) * dego^-1/2
__device__ float g_h1[NN * HID];   // h1pre -> h1
__device__ int   g_dego[NN];
__device__ int   g_degi[NN];
__device__ int   g_cursor[NN];
__device__ int   g_esrc[NE];       // src sorted by dst
__device__ int   g_edst[NE];       // dst sorted
__device__ int   g_bsum[NB_SCAN];
__device__ int   g_boff[512];
__device__ int   g_ctr;
__device__ float g_sum[HID];
__device__ float g_ssq[HID];
__device__ float g_bna[HID];
__device__ float g_bnc[HID];

// tf32 helpers (base sm_80+ PTX, no 'a'-suffix features)
__device__ __forceinline__ uint32_t f2tf32(float v) {
    uint32_t r;
    asm("cvt.rna.tf32.f32 %0, %1;" : "=r"(r) : "f"(v));
    return r;
}

#define MMA_TF32(d, A0, A1, A2, A3, B0, B1) \
    asm volatile("mma.sync.aligned.m16n8k8.row.col.f32.tf32.tf32.f32 " \
        "{%0,%1,%2,%3}, {%4,%5,%6,%7}, {%8,%9}, {%0,%1,%2,%3};" \
        : "+f"((d)[0]), "+f"((d)[1]), "+f"((d)[2]), "+f"((d)[3]) \
        : "r"(A0), "r"(A1), "r"(A2), "r"(A3), "r"(B0), "r"(B1))

// ---------------- init: zero degrees + BN accumulators + counter ----------------
__global__ void k_init() {
    int i = blockIdx.x * blockDim.x + threadIdx.x;
    if (i < NN) { g_dego[i] = 0; g_degi[i] = 0; }
    if (i < HID) { g_sum[i] = 0.f; g_ssq[i] = 0.f; }
    if (i == 0) g_ctr = 0;
}

// ---------------- degree counting ----------------
__global__ void k_degree(const int* __restrict__ src, const int* __restrict__ dst) {
    int e = blockIdx.x * blockDim.x + threadIdx.x;
    if (e < NE) {
        atomicAdd(&g_dego[src[e]], 1);
        atomicAdd(&g_degi[dst[e]], 1);
    }
}

// ---------------- scanA: per-block sums; last block scans block sums ----------------
__global__ void k_scanA() {
    __shared__ int sh[256];
    __shared__ int bufA[512], bufB[512];
    __shared__ int last;
    int t = threadIdx.x;
    int i = blockIdx.x * 256 + t;
    sh[t] = (i < NN) ? g_degi[i] : 0;
    __syncthreads();
    for (int off = 128; off; off >>= 1) {
        if (t < off) sh[t] += sh[t + off];
        __syncthreads();
    }
    if (t == 0) {
        g_bsum[blockIdx.x] = sh[0];
        __threadfence();
        int old = atomicAdd(&g_ctr, 1);
        last = (old == gridDim.x - 1) ? 1 : 0;
    }
    __syncthreads();
    if (last) {
        // inclusive scan of 391 block sums (padded to 512), double-buffer
        int v0 = (t < NB_SCAN) ? ((volatile int*)g_bsum)[t] : 0;
        int v1 = (t + 256 < NB_SCAN) ? ((volatile int*)g_bsum)[t + 256] : 0;
        bufA[t] = v0; bufA[t + 256] = v1;
        __syncthreads();
        int* s = bufA; int* d = bufB;
        for (int off = 1; off < 512; off <<= 1) {
            d[t] = s[t] + ((t >= off) ? s[t - off] : 0);
            d[t + 256] = s[t + 256] + s[t + 256 - off];
            __syncthreads();
            int* tmp = s; s = d; d = tmp;
        }
        g_boff[t] = s[t] - v0;             // exclusive
        g_boff[t + 256] = s[t + 256] - v1;
    }
}

__global__ void k_scanC() {
    __shared__ int sh[256];
    int t = threadIdx.x;
    int i = blockIdx.x * 256 + t;
    int v = (i < NN) ? g_degi[i] : 0;
    sh[t] = v;
    __syncthreads();
    for (int off = 1; off < 256; off <<= 1) {
        int a = (t >= off) ? sh[t - off] : 0;
        __syncthreads();
        sh[t] += a;
        __syncthreads();
    }
    int excl = sh[t] - v + g_boff[blockIdx.x];
    if (i < NN) g_cursor[i] = excl;
}

__global__ void k_fill(const int* __restrict__ src, const int* __restrict__ dst) {
    int e = blockIdx.x * blockDim.x + threadIdx.x;
    if (e < NE) {
        int d = dst[e];
        int p = atomicAdd(&g_cursor[d], 1);
        g_esrc[p] = src[e];
        g_edst[p] = d;
    }
}

// ======= tf32-split tensor-core GEMM: C[N,64] = A[N,K] @ W[K,64] =======
// MODE 0: A = x,    writes h0 = acc+fc_b AND h1pre = (h0+b1)*S -> g_h1   (K=128)
// MODE 1: A = g_h0, writes t = acc * dego^-1/2                          (K=64)
// MODE 2: A = g_h1, writes t AND h2pre = (h1+b2)*S -> g_h0              (K=64)
template <int MODE>
__global__ __launch_bounds__(256) void k_gemm(const float* __restrict__ Ain,
                                              const float* __restrict__ W,
                                              const float* __restrict__ bias,
                                              const float* __restrict__ bias2) {
    constexpr int K = (MODE == 0) ? FIN : HID;
    constexpr int NCH = K / 64;
    constexpr int SA = 68;
    constexpr int SB = 72;

    extern __shared__ float smem[];
    float* Ah = smem;                    // [128][SA]
    float* Al = Ah + 128 * SA;
    float* Bh = Al + 128 * SA;           // [64][SB]
    float* Bl = Bh + 64 * SB;

    const float* A = (MODE == 0) ? Ain : ((MODE == 1) ? (const float*)g_h0
                                                      : (const float*)g_h1);
    float* C = (MODE == 0) ? (float*)g_h0 : (float*)g_t;

    const int t = threadIdx.x;
    const int lane = t & 31;
    const int g = lane >> 2;        // groupID 0..7
    const int tig = lane & 3;       // thread-in-group 0..3
    const int warp = t >> 5;
    const int wm = warp & 3;        // 32-row group
    const int wn = warp >> 2;       // 32-col group
    const int r0 = blockIdx.x * 128;

    float acc[2][4][4];
#pragma unroll
    for (int m = 0; m < 2; m++)
#pragma unroll
        for (int nt = 0; nt < 4; nt++)
#pragma unroll
            for (int i = 0; i < 4; i++) acc[m][nt][i] = 0.f;

    const int arow = t & 127;
    const int khalf = t >> 7;
    const int rload = min(r0 + arow, NN - 1);
    const float4* A4 = (const float4*)(A + (size_t)rload * K);
    const float4* W4 = (const float4*)W;

#pragma unroll
    for (int ch = 0; ch < NCH; ch++) {
        if (ch > 0) __syncthreads();
#pragma unroll
        for (int j = 0; j < 8; j++) {
            float4 v = A4[ch * 16 + khalf * 8 + j];
            float4 hi = make_float4(
                __uint_as_float(f2tf32(v.x)), __uint_as_float(f2tf32(v.y)),
                __uint_as_float(f2tf32(v.z)), __uint_as_float(f2tf32(v.w)));
            float4 lo = make_float4(
                __uint_as_float(f2tf32(v.x - hi.x)), __uint_as_float(f2tf32(v.y - hi.y)),
                __uint_as_float(f2tf32(v.z - hi.z)), __uint_as_float(f2tf32(v.w - hi.w)));
            int off = arow * SA + khalf * 32 + j * 4;
            *(float4*)&Ah[off] = hi;
            *(float4*)&Al[off] = lo;
        }
#pragma unroll
        for (int j = 0; j < 4; j++) {
            int idx = t + j * 256;
            int kr = idx >> 4, c4 = idx & 15;
            float4 v = W4[(size_t)(ch * 64 + kr) * (HID / 4) + c4];
            float4 hi = make_float4(
                __uint_as_float(f2tf32(v.x)), __uint_as_float(f2tf32(v.y)),
                __uint_as_float(f2tf32(v.z)), __uint_as_float(f2tf32(v.w)));
            float4 lo = make_float4(
                __uint_as_float(f2tf32(v.x - hi.x)), __uint_as_float(f2tf32(v.y - hi.y)),
                __uint_as_float(f2tf32(v.z - hi.z)), __uint_as_float(f2tf32(v.w - hi.w)));
            int off = kr * SB + c4 * 4;
            *(float4*)&Bh[off] = hi;
            *(float4*)&Bl[off] = lo;
        }
        __syncthreads();

#pragma unroll
        for (int k0 = 0; k0 < 64; k0 += 8) {
            uint32_t bh0[4], bh1[4], bl0[4], bl1[4];
#pragma unroll
            for (int nt = 0; nt < 4; nt++) {
                int col = wn * 32 + nt * 8 + g;
                bh0[nt] = __float_as_uint(Bh[(k0 + tig) * SB + col]);
                bh1[nt] = __float_as_uint(Bh[(k0 + tig + 4) * SB + col]);
                bl0[nt] = __float_as_uint(Bl[(k0 + tig) * SB + col]);
                bl1[nt] = __float_as_uint(Bl[(k0 + tig + 4) * SB + col]);
            }
#pragma unroll
            for (int m = 0; m < 2; m++) {
                int rb = wm * 32 + m * 16;
                uint32_t ah0 = __float_as_uint(Ah[(rb + g) * SA + k0 + tig]);
                uint32_t ah1 = __float_as_uint(Ah[(rb + g + 8) * SA + k0 + tig]);
                uint32_t ah2 = __float_as_uint(Ah[(rb + g) * SA + k0 + tig + 4]);
                uint32_t ah3 = __float_as_uint(Ah[(rb + g + 8) * SA + k0 + tig + 4]);
                uint32_t al0 = __float_as_uint(Al[(rb + g) * SA + k0 + tig]);
                uint32_t al1 = __float_as_uint(Al[(rb + g + 8) * SA + k0 + tig]);
                uint32_t al2 = __float_as_uint(Al[(rb + g) * SA + k0 + tig + 4]);
                uint32_t al3 = __float_as_uint(Al[(rb + g + 8) * SA + k0 + tig + 4]);
#pragma unroll
                for (int nt = 0; nt < 4; nt++) {
                    MMA_TF32(acc[m][nt], ah0, ah1, ah2, ah3, bh0[nt], bh1[nt]);
                    MMA_TF32(acc[m][nt], al0, al1, al2, al3, bh0[nt], bh1[nt]);
                    MMA_TF32(acc[m][nt], ah0, ah1, ah2, ah3, bl0[nt], bl1[nt]);
                }
            }
        }
    }

    // --- epilogue ---
    float scl = d_SCALE;
#pragma unroll
    for (int m = 0; m < 2; m++) {
        int lr1 = wm * 32 + m * 16 + g;
        int lr2 = lr1 + 8;
        int r1 = r0 + lr1;
        int r2 = r0 + lr2;
        if (MODE == 0) {
#pragma unroll
            for (int nt = 0; nt < 4; nt++) {
                int col = wn * 32 + nt * 8 + 2 * tig;
                float2 bb = __ldg((const float2*)&bias[col]);
                float2 b1v = __ldg((const float2*)&bias2[col]);
                if (r1 < NN) {
                    float2 o = make_float2(acc[m][nt][0] + bb.x, acc[m][nt][1] + bb.y);
                    *(float2*)&C[(size_t)r1 * HID + col] = o;
                    float2 hp = make_float2((o.x + b1v.x) * scl, (o.y + b1v.y) * scl);
                    *(float2*)&g_h1[(size_t)r1 * HID + col] = hp;
                }
                if (r2 < NN) {
                    float2 o = make_float2(acc[m][nt][2] + bb.x, acc[m][nt][3] + bb.y);
                    *(float2*)&C[(size_t)r2 * HID + col] = o;
                    float2 hp = make_float2((o.x + b1v.x) * scl, (o.y + b1v.y) * scl);
                    *(float2*)&g_h1[(size_t)r2 * HID + col] = hp;
                }
            }
        } else {
            float s1 = (r1 < NN) ? rsqrtf((float)max(g_dego[r1], 1)) : 0.f;
            float s2 = (r2 < NN) ? rsqrtf((float)max(g_dego[r2], 1)) : 0.f;
#pragma unroll
            for (int nt = 0; nt < 4; nt++) {
                int col = wn * 32 + nt * 8 + 2 * tig;
                if (r1 < NN) {
                    float2 o = make_float2(acc[m][nt][0] * s1, acc[m][nt][1] * s1);
                    *(float2*)&C[(size_t)r1 * HID + col] = o;
                }
                if (r2 < NN) {
                    float2 o = make_float2(acc[m][nt][2] * s2, acc[m][nt][3] * s2);
                    *(float2*)&C[(size_t)r2 * HID + col] = o;
                }
                if (MODE == 2) {
                    // h2pre = (h1 + b2) * S ; h1 recovered from smem hi+lo
                    float2 b2v = __ldg((const float2*)&bias2[col]);
                    if (r1 < NN) {
                        float h1a = Ah[lr1 * SA + col] + Al[lr1 * SA + col];
                        float h1b = Ah[lr1 * SA + col + 1] + Al[lr1 * SA + col + 1];
                        float2 hp = make_float2((h1a + b2v.x) * scl, (h1b + b2v.y) * scl);
                        *(float2*)&g_h0[(size_t)r1 * HID + col] = hp;
                    }
                    if (r2 < NN) {
                        float h1a = Ah[lr2 * SA + col] + Al[lr2 * SA + col];
                        float h1b = Ah[lr2 * SA + col + 1] + Al[lr2 * SA + col + 1];
                        float2 hp = make_float2((h1a + b2v.x) * scl, (h1b + b2v.y) * scl);
                        *(float2*)&g_h0[(size_t)r2 * HID + col] = hp;
                    }
                }
            }
        }
    }
}

// ======= sorted-edge segmented scatter: H[dst] += S*nrmi[dst] * sum(t[src]) =======
// TARGET 1 -> g_h1, TARGET 0 -> g_h0
template <int TARGET>
__global__ void k_scatter_sorted() {
    int idx = blockIdx.x * blockDim.x + threadIdx.x;   // exact: NE/EPT*16
    int c = idx & 15;
    int chunk = idx >> 4;
    int p0 = chunk * EPT;

    float* H = (TARGET == 1) ? (float*)g_h1 : (float*)g_h0;
    const float4* T4 = (const float4*)g_t;
    float4 acc = make_float4(0.f, 0.f, 0.f, 0.f);
    int dprev = __ldg(&g_edst[p0]);

#pragma unroll
    for (int j = 0; j < EPT; j++) {
        int p = p0 + j;
        int s = __ldg(&g_esrc[p]);
        int d = __ldg(&g_edst[p]);
        if (d != dprev) {
            float w = d_SCALE * rsqrtf((float)max(__ldg(&g_degi[dprev]), 1));
            float* q = &H[(size_t)dprev * HID + c * 4];
            asm volatile("red.global.add.v4.f32 [%0], {%1,%2,%3,%4};"
                         :: "l"(q), "f"(acc.x * w), "f"(acc.y * w), "f"(acc.z * w), "f"(acc.w * w)
                         : "memory");
            acc = make_float4(0.f, 0.f, 0.f, 0.f);
            dprev = d;
        }
        float4 v = T4[(size_t)s * 16 + c];
        acc.x += v.x; acc.y += v.y; acc.z += v.z; acc.w += v.w;
    }
    float w = d_SCALE * rsqrtf((float)max(__ldg(&g_degi[dprev]), 1));
    float* q = &H[(size_t)dprev * HID + c * 4];
    asm volatile("red.global.add.v4.f32 [%0], {%1,%2,%3,%4};"
                 :: "l"(q), "f"(acc.x * w), "f"(acc.y * w), "f"(acc.z * w), "f"(acc.w * w)
                 : "memory");
}

// ------- BN partial sums over h2 (= g_h0 after scatter2) -------
__global__ __launch_bounds__(256) void k_bnstats() {
    const int T = gridDim.x * blockDim.x;
    int tg = blockIdx.x * blockDim.x + threadIdx.x;
    float4 s = make_float4(0.f, 0.f, 0.f, 0.f);
    float4 ss = make_float4(0.f, 0.f, 0.f, 0.f);
    for (int idx = tg; idx < NN * (HID / 4); idx += T) {
        float4 v = ((const float4*)g_h0)[idx];
        s.x += v.x; s.y += v.y; s.z += v.z; s.w += v.w;
        ss.x += v.x * v.x; ss.y += v.y * v.y; ss.z += v.z * v.z; ss.w += v.w * v.w;
    }
    __shared__ float4 sh[256];
    sh[threadIdx.x] = s;
    __syncthreads();
    if (threadIdx.x < 16) {
        float4 tot = sh[threadIdx.x];
#pragma unroll
        for (int j = 1; j < 16; j++) {
            float4 o = sh[threadIdx.x + j * 16];
            tot.x += o.x; tot.y += o.y; tot.z += o.z; tot.w += o.w;
        }
        atomicAdd(&g_sum[threadIdx.x * 4 + 0], tot.x);
        atomicAdd(&g_sum[threadIdx.x * 4 + 1], tot.y);
        atomicAdd(&g_sum[threadIdx.x * 4 + 2], tot.z);
        atomicAdd(&g_sum[threadIdx.x * 4 + 3], tot.w);
    }
    __syncthreads();
    sh[threadIdx.x] = ss;
    __syncthreads();
    if (threadIdx.x < 16) {
        float4 tot = sh[threadIdx.x];
#pragma unroll
        for (int j = 1; j < 16; j++) {
            float4 o = sh[threadIdx.x + j * 16];
            tot.x += o.x; tot.y += o.y; tot.z += o.z; tot.w += o.w;
        }
        atomicAdd(&g_ssq[threadIdx.x * 4 + 0], tot.x);
        atomicAdd(&g_ssq[threadIdx.x * 4 + 1], tot.y);
        atomicAdd(&g_ssq[threadIdx.x * 4 + 2], tot.z);
        atomicAdd(&g_ssq[threadIdx.x * 4 + 3], tot.w);
    }
}

__global__ void k_bn_final(const float* __restrict__ gamma, const float* __restrict__ beta) {
    int f = threadIdx.x;
    float mu = g_sum[f] * (1.0f / NN);
    float var = g_ssq[f] * (1.0f / NN) - mu * mu;
    float a = gamma[f] * rsqrtf(var + BN_EPS);
    g_bna[f] = a;
    g_bnc[f] = beta[f] - mu * a;
}

__global__ void k_out(float* __restrict__ out) {
    int idx = blockIdx.x * blockDim.x + threadIdx.x;
    if (idx >= NN * (HID / 4)) return;
    int c4 = idx & 15;
    float4 h = ((const float4*)g_h0)[idx];
    float4 a = ((const float4*)g_bna)[c4];
    float4 c = ((const float4*)g_bnc)[c4];
    float4 r;
    r.x = h.x * a.x + c.x;
    r.y = h.y * a.y + c.y;
    r.z = h.z * a.z + c.z;
    r.w = h.w * a.w + c.w;
    ((float4*)out)[idx] = r;
}

// ---------------- launch ----------------
extern "C" void kernel_launch(void* const* d_in, const int* in_sizes, int n_in,
                              void* d_out, int out_size) {
    const int* src = (const int*)d_in[0];
    const int* dst = (const int*)d_in[1];
    const float* x = (const float*)d_in[2];
    const float* fc_w = (const float*)d_in[3];
    const float* fc_b = (const float*)d_in[4];
    const float* w1 = (const float*)d_in[5];
    const float* b1 = (const float*)d_in[6];
    const float* w2 = (const float*)d_in[7];
    const float* b2 = (const float*)d_in[8];
    const float* gamma = (const float*)d_in[9];
    const float* beta = (const float*)d_in[10];
    float* out = (float*)d_out;

    const int SMEM = (2 * 128 * 68 + 2 * 64 * 72) * 4;   // 106496 bytes
    cudaFuncSetAttribute(k_gemm<0>, cudaFuncAttributeMaxDynamicSharedMemorySize, SMEM);
    cudaFuncSetAttribute(k_gemm<1>, cudaFuncAttributeMaxDynamicSharedMemorySize, SMEM);
    cudaFuncSetAttribute(k_gemm<2>, cudaFuncAttributeMaxDynamicSharedMemorySize, SMEM);

    const int nb_vec = (NN * (HID / 4) + 255) / 256;     // 6250
    const int nb_edge = (NE + 255) / 256;
    const int nb_gemm = (NN + 127) / 128;                // 782
    const int nb_sscat = (NE / EPT) * 16 / 256;          // 6250 (exact)

    k_init<<<NB_SCAN, 256>>>();
    k_degree<<<nb_edge, 256>>>(src, dst);

    // dst-sorted edge list (scanB folded into scanA's last block)
    k_scanA<<<NB_SCAN, 256>>>();
    k_scanC<<<NB_SCAN, 256>>>();
    k_fill<<<nb_edge, 256>>>(src, dst);

    // fc: h0 = x@fc_w + fc_b ; h1pre = (h0+b1)*S
    k_gemm<0><<<nb_gemm, 256, SMEM>>>(x, fc_w, fc_b, b1);

    // conv1: t = (h0@w1)*nrmo ; scatter S*nrmi*t onto h1pre -> h1
    k_gemm<1><<<nb_gemm, 256, SMEM>>>(nullptr, w1, nullptr, nullptr);
    k_scatter_sorted<1><<<nb_sscat, 256>>>();

    // conv2: t = (h1@w2)*nrmo ; h2pre = (h1+b2)*S ; scatter onto -> h2
    k_gemm<2><<<nb_gemm, 256, SMEM>>>(nullptr, w2, nullptr, b2);
    k_scatter_sorted<0><<<nb_sscat, 256>>>();

    k_bnstats<<<256, 256>>>();
    k_bn_final<<<1, 64>>>(gamma, beta);
    k_out<<<nb_vec, 256>>>(out);
}